// round 2
// baseline (speedup 1.0000x reference)
#include <cuda_runtime.h>
#include <cstdint>
#include <cstddef>

#define HH 128
#define WW 128
#define CC 64
#define CH2 128
#define BBATCH 16
#define TSTEPS 16

// Precomputed frequency-domain fields: {Ar*scale, Ai*scale, Br, Bi} per (h,w,c)
__device__ float4 g_fields[HH * WW * CC];

// ---------------------------------------------------------------------------
// Kernel 1: direct DFT of the zero-padded 7x7 complex kernels (A and B),
// plus the magnitude-based stabilization of A.
// A_f[c,u,v] = sum_{p,q} (kr + i ki) * exp(-2*pi*i*(u*(p+60) + v*(q+60))/128)
// ---------------------------------------------------------------------------
__global__ void fields_kernel(const float* __restrict__ A_real,
                              const float* __restrict__ A_imag,
                              const float* __restrict__ B_real,
                              const float* __restrict__ B_imag) {
    int uv = blockIdx.x;          // 0 .. 128*128-1
    int u = uv >> 7;              // h frequency index
    int v = uv & 127;             // w frequency index
    int c = threadIdx.x;          // 0..63

    __shared__ float ct[128], st[128];
    for (int m = c; m < 128; m += 64) {
        float s, co;
        sincospif((float)m * (1.0f / 64.0f), &s, &co);  // angle = 2*pi*m/128
        ct[m] = co;
        st[m] = s;
    }
    __syncthreads();

    float ar = 0.f, ai = 0.f, br = 0.f, bi = 0.f;
    int base = c * 49;
#pragma unroll
    for (int p = 0; p < 7; p++) {
#pragma unroll
        for (int q = 0; q < 7; q++) {
            int m = (u * (p + 60) + v * (q + 60)) & 127;
            float co = ct[m], si = st[m];
            float kr = A_real[base + p * 7 + q];
            float ki = A_imag[base + p * 7 + q];
            // (kr + i*ki) * (cos - i*sin)
            ar += kr * co + ki * si;
            ai += ki * co - kr * si;
            kr = B_real[base + p * 7 + q];
            ki = B_imag[base + p * 7 + q];
            br += kr * co + ki * si;
            bi += ki * co - kr * si;
        }
    }
    float mag = sqrtf(ar * ar + ai * ai + 1e-8f);
    float scale = 0.95f * (1.0f / (1.0f + __expf(-mag))) / (mag + 1e-8f);
    g_fields[uv * CC + c] = make_float4(ar * scale, ai * scale, br, bi);
}

// ---------------------------------------------------------------------------
// Fused main kernel: tf32 tensor-core GEMM for the three gates + gated
// complex recurrence epilogue.
//
// Per CTA: 64 positions = (16 batches x 4 w) at fixed h. 512 threads.
// GEMM: Out[64 x 384] = X[64 x 128] @ Wcat[128 x 384], Wcat = [Wf | Wi | Wd].
// 16 warps: 4 along M (m16 each) x 4 along N (n96 each). mma m16n8k4 tf32.
// W k-chunks (8 x 384) double-buffered via cp.async (2-deep pipeline).
// ---------------------------------------------------------------------------

#define XS_STRIDE 132            // 128 + 4 pad: conflict-free a-frag loads
#define XS_FLOATS (64 * XS_STRIDE)          // 8448
#define WS_STRIDE 392            // 384 + 8 pad: conflict-free b-frag loads
#define WS_BUF (8 * WS_STRIDE)              // 3136
#define WS_FLOATS (2 * WS_BUF)              // 6272
#define GS_STRIDE 388            // 384 + 4 pad: low-conflict mma stores
#define GS_FLOATS (64 * GS_STRIDE)          // 24832
#define SMEM_FLOATS (XS_FLOATS + WS_FLOATS + GS_FLOATS)   // 39552
#define SMEM_BYTES (SMEM_FLOATS * 4)                      // 158208

__device__ __forceinline__ unsigned f2tf32(float x) {
    unsigned r;
    asm("cvt.rna.tf32.f32 %0, %1;" : "=r"(r) : "f"(x));
    return r;
}

__device__ __forceinline__ void mma_tf32_k4(float d[4], unsigned a0, unsigned a1, unsigned b0) {
    asm volatile(
        "mma.sync.aligned.m16n8k4.row.col.f32.tf32.tf32.f32 "
        "{%0,%1,%2,%3}, {%4,%5}, {%6}, {%0,%1,%2,%3};"
        : "+f"(d[0]), "+f"(d[1]), "+f"(d[2]), "+f"(d[3])
        : "r"(a0), "r"(a1), "r"(b0));
}

__device__ __forceinline__ void cp8(float* dst, const float* src) {
    unsigned s = (unsigned)__cvta_generic_to_shared(dst);
    asm volatile("cp.async.ca.shared.global [%0], [%1], 8;" :: "r"(s), "l"(src));
}

__device__ __forceinline__ void stage_w_chunk(float* wbuf, int kc, int tid,
                                              const float* __restrict__ Wf,
                                              const float* __restrict__ Wi,
                                              const float* __restrict__ Wd) {
    // copy Wcat[kc*8 .. kc*8+7][0..383] -> wbuf[row*WS_STRIDE + col]
    // 8 rows * 384 cols = 1536 float2 ops / 512 threads = 3 each
#pragma unroll
    for (int j = 0; j < 3; j++) {
        int i = tid + j * 512;        // 0..1535
        int row = i / 192;            // 0..7
        int col = (i % 192) * 2;      // 0..382, even
        int mt = col >> 7;            // which matrix
        int cc = col & 127;
        const float* src = (mt == 0) ? Wf : ((mt == 1) ? Wi : Wd);
        cp8(&wbuf[row * WS_STRIDE + col], src + (size_t)(kc * 8 + row) * CH2 + cc);
    }
}

__global__ void __launch_bounds__(512, 1)
fused_main_kernel(const float* __restrict__ x,
                  const float* __restrict__ Wf, const float* __restrict__ bf,
                  const float* __restrict__ Wi, const float* __restrict__ bi,
                  const float* __restrict__ Wd, const float* __restrict__ bd,
                  float* __restrict__ out) {
    extern __shared__ float sm[];
    float* Xs  = sm;                            // [64][XS_STRIDE] fp32
    float* Wsm = sm + XS_FLOATS;                // 2 x [8][WS_STRIDE] fp32
    float* Gs  = sm + XS_FLOATS + WS_FLOATS;    // [64][GS_STRIDE] fp32 gates

    int tid = threadIdx.x;
    int bid = blockIdx.x;
    int h  = bid >> 5;
    int w0 = (bid & 31) * 4;

    // ---- load X tile: 64 rows (b = p&15, dw = p>>4) x 128 floats ----
    for (int i = tid; i < 64 * 32; i += 512) {
        int p = i >> 5, c4 = i & 31;
        int b = p & 15, dw = p >> 4;
        const float4* src =
            (const float4*)(x + (size_t)((b * HH + h) * WW + w0 + dw) * CH2);
        *(float4*)&Xs[p * XS_STRIDE + c4 * 4] = src[c4];
    }

    // ---- prologue: stage W chunks 0 and 1 (2-deep pipeline) ----
    stage_w_chunk(Wsm, 0, tid, Wf, Wi, Wd);
    asm volatile("cp.async.commit_group;");
    stage_w_chunk(Wsm + WS_BUF, 1, tid, Wf, Wi, Wd);
    asm volatile("cp.async.commit_group;");

    int wid = tid >> 5, lane = tid & 31;
    int wm = wid & 3, wn = wid >> 2;
    int m0 = wm * 16, n0 = wn * 96;
    int gid = lane >> 2, tig = lane & 3;

    float acc[12][4];
#pragma unroll
    for (int t = 0; t < 12; t++) {
        acc[t][0] = 0.f; acc[t][1] = 0.f; acc[t][2] = 0.f; acc[t][3] = 0.f;
    }

    int xr0 = (m0 + gid) * XS_STRIDE;
    int xr1 = (m0 + gid + 8) * XS_STRIDE;

    // ---- K loop: 16 chunks of k=8 (2 x k4 mma each) ----
    for (int kc = 0; kc < 16; kc++) {
        // chunk kc must be resident; allow the most recent commit (kc+1) in flight
        if (kc < 15) {
            asm volatile("cp.async.wait_group 1;");
        } else {
            asm volatile("cp.async.wait_group 0;");
        }
        __syncthreads();   // all warps see chunk kc; X tile ready on kc==0
        const float* Wb = Wsm + (kc & 1) * WS_BUF;

        unsigned a00 = f2tf32(Xs[xr0 + kc * 8 + tig]);
        unsigned a10 = f2tf32(Xs[xr1 + kc * 8 + tig]);
        unsigned a01 = f2tf32(Xs[xr0 + kc * 8 + 4 + tig]);
        unsigned a11 = f2tf32(Xs[xr1 + kc * 8 + 4 + tig]);
#pragma unroll
        for (int t = 0; t < 12; t++) {
            unsigned b0 = f2tf32(Wb[tig * WS_STRIDE + n0 + t * 8 + gid]);
            unsigned b1 = f2tf32(Wb[(tig + 4) * WS_STRIDE + n0 + t * 8 + gid]);
            mma_tf32_k4(acc[t], a00, a10, b0);
            mma_tf32_k4(acc[t], a01, a11, b1);
        }

        if (kc < 14) {
            __syncthreads();   // buffer kc&1 fully consumed by every warp
            stage_w_chunk(Wsm + (kc & 1) * WS_BUF, kc + 2, tid, Wf, Wi, Wd);
            asm volatile("cp.async.commit_group;");
        }
    }

    // ---- write gate pre-activations to smem (position-major) ----
#pragma unroll
    for (int t = 0; t < 12; t++) {
        int col = n0 + t * 8 + 2 * tig;
        Gs[(m0 + gid) * GS_STRIDE + col]         = acc[t][0];
        Gs[(m0 + gid) * GS_STRIDE + col + 1]     = acc[t][1];
        Gs[(m0 + gid + 8) * GS_STRIDE + col]     = acc[t][2];
        Gs[(m0 + gid + 8) * GS_STRIDE + col + 1] = acc[t][3];
    }
    __syncthreads();

    // ---- epilogue: gates -> gated complex recurrence (T=16) ----
    for (int it = 0; it < 8; it++) {
        int p = it * 8 + (tid >> 6);   // 0..63
        int c = tid & 63;              // 0..63
        const float* Gp = Gs + p * GS_STRIDE;

        float zfr = Gp[c]        + bf[c]      + 2.0f;
        float zfi = Gp[c + 64]   + bf[c + 64] + 2.0f;
        float zir = Gp[128 + c]  + bi[c];
        float zii = Gp[192 + c]  + bi[c + 64];
        float zdr = Gp[256 + c]  + bd[c];
        float zdi = Gp[320 + c]  + bd[c + 64];

        float fgr = 1.0f / (1.0f + __expf(-zfr));
        float fgi = 1.0f / (1.0f + __expf(-zfi));
        float igr = 1.0f / (1.0f + __expf(-zir));
        float igi = 1.0f / (1.0f + __expf(-zii));
        float dr  = 0.1f * (fmaxf(zdr, 0.f) + log1pf(__expf(-fabsf(zdr))));
        float di  = 0.1f * (fmaxf(zdi, 0.f) + log1pf(__expf(-fabsf(zdi))));

        float xr = Xs[p * XS_STRIDE + c];
        float xi = Xs[p * XS_STRIDE + 64 + c];

        int dw = p >> 4, b = p & 15;
        float4 f = g_fields[(h * WW + w0 + dw) * CC + c];  // {Ar,Ai,Br,Bi}

        float Bxr = f.z * xr - f.w * xi;
        float Bxi = f.z * xi + f.w * xr;
        float inr = dr * igr * Bxr;
        float ini = di * igi * Bxi;

        float hr = 0.f, hi = 0.f;
#pragma unroll
        for (int t = 0; t < TSTEPS; t++) {
            float Ahr = f.x * hr - f.y * hi;
            float Ahi = f.x * hi + f.y * hr;
            hr = fgr * Ahr + inr;
            hi = fgi * Ahi + ini;
        }

        size_t o = (size_t)((b * HH + h) * WW + w0 + dw) * CH2 + c;
        out[o]      = hr;
        out[o + 64] = hi;
    }
}

extern "C" void kernel_launch(void* const* d_in, const int* in_sizes, int n_in,
                              void* d_out, int out_size) {
    const float* x  = (const float*)d_in[0];
    const float* Wf = (const float*)d_in[1];
    const float* bf = (const float*)d_in[2];
    const float* Wi = (const float*)d_in[3];
    const float* bi = (const float*)d_in[4];
    const float* Wd = (const float*)d_in[5];
    const float* bd = (const float*)d_in[6];
    const float* Ar = (const float*)d_in[7];
    const float* Ai = (const float*)d_in[8];
    const float* Br = (const float*)d_in[9];
    const float* Bi = (const float*)d_in[10];
    float* out = (float*)d_out;

    fields_kernel<<<HH * WW, CC>>>(Ar, Ai, Br, Bi);

    cudaFuncSetAttribute(fused_main_kernel,
                         cudaFuncAttributeMaxDynamicSharedMemorySize, SMEM_BYTES);
    fused_main_kernel<<<HH * (WW / 4), 512, SMEM_BYTES>>>(x, Wf, bf, Wi, bi, Wd, bd, out);
}

// round 3
// speedup vs baseline: 1.7516x; 1.7516x over previous
#include <cuda_runtime.h>
#include <cstdint>
#include <cstddef>

#define HH 128
#define WW 128
#define CC 64
#define CH2 128
#define TSTEPS 16

// Precomputed frequency-domain fields: {Ar*scale, Ai*scale, Br, Bi} per (h,w,c)
__device__ float4 g_fields[HH * WW * CC];
// Pre-permuted, tf32-converted, fragment-interleaved Wcat:
// [kc(8)][grp(2)][col'(384)][p(4)][e(2)] ; k = kc*16 + grp*8 + p + 4e
// col' = wn*48 + b*8 + r ; gate g=b/2, ri=b%2, c = wn*8+r ; src = W_g[k][ri*64+c]
__device__ float g_wp[8 * 6144];

__device__ __forceinline__ unsigned f2tf32(float x) {
    unsigned r;
    asm("cvt.rna.tf32.f32 %0, %1;" : "=r"(r) : "f"(x));
    return r;
}

// ---------------------------------------------------------------------------
// Prep kernel: build g_wp (one-time, 48K elements)
// ---------------------------------------------------------------------------
__global__ void wprep_kernel(const float* __restrict__ Wf,
                             const float* __restrict__ Wi,
                             const float* __restrict__ Wd) {
    int idx = blockIdx.x * 512 + threadIdx.x;   // 0 .. 49151
    int kc = idx / 6144, r1 = idx % 6144;
    int grp = r1 / 3072, r2 = r1 % 3072;
    int col = r2 >> 3, p = (r2 & 7) >> 1, e = r2 & 1;
    int k = kc * 16 + grp * 8 + p + 4 * e;
    int wn = col / 48, bb = (col % 48) >> 3, r = col & 7;
    int g = bb >> 1, ri = bb & 1;
    int c = wn * 8 + r;
    const float* W = (g == 0) ? Wf : ((g == 1) ? Wi : Wd);
    g_wp[idx] = __uint_as_float(f2tf32(W[k * CH2 + ri * 64 + c]));
}

// ---------------------------------------------------------------------------
// Fields kernel: direct DFT of zero-padded 7x7 complex kernels + A stabilization.
// 256 threads/block, 4 uv per block, A/B kernels cached in smem.
// ---------------------------------------------------------------------------
__global__ void fields_kernel(const float* __restrict__ A_real,
                              const float* __restrict__ A_imag,
                              const float* __restrict__ B_real,
                              const float* __restrict__ B_imag) {
    extern __shared__ float fs[];
    float* sAr = fs;                 // 3136
    float* sAi = fs + 3136;
    float* sBr = fs + 6272;
    float* sBi = fs + 9408;
    float* ct  = fs + 12544;         // 128
    float* st  = fs + 12672;         // 128

    int tid = threadIdx.x;
    for (int i = tid; i < 3136; i += 256) {
        sAr[i] = A_real[i]; sAi[i] = A_imag[i];
        sBr[i] = B_real[i]; sBi[i] = B_imag[i];
    }
    if (tid < 128) {
        float s, co;
        sincospif((float)tid * (1.0f / 64.0f), &s, &co);
        ct[tid] = co; st[tid] = s;
    }
    __syncthreads();

    int c = tid & 63, lc = tid >> 6;
    int uv = blockIdx.x * 4 + lc;
    int u = uv >> 7, v = uv & 127;

    float ar = 0.f, ai = 0.f, br = 0.f, bi = 0.f;
    int base = c * 49;
#pragma unroll
    for (int p = 0; p < 7; p++) {
#pragma unroll
        for (int q = 0; q < 7; q++) {
            int m = (u * (p + 60) + v * (q + 60)) & 127;
            float co = ct[m], si = st[m];
            float kr = sAr[base + p * 7 + q];
            float ki = sAi[base + p * 7 + q];
            ar += kr * co + ki * si;
            ai += ki * co - kr * si;
            kr = sBr[base + p * 7 + q];
            ki = sBi[base + p * 7 + q];
            br += kr * co + ki * si;
            bi += ki * co - kr * si;
        }
    }
    float mag = sqrtf(ar * ar + ai * ai + 1e-8f);
    float scale = 0.95f * (1.0f / (1.0f + __expf(-mag))) / (mag + 1e-8f);
    g_fields[uv * CC + c] = make_float4(ar * scale, ai * scale, br, bi);
}

// ---------------------------------------------------------------------------
// Fused main kernel.
// CTA: 512 threads, 64 positions (16 b x 4 w at fixed h).
// 16 warps = wm(2) x wn(8); warp tile m32 x n48 (permuted cols, 6 gate blocks).
// mma m16n8k8 tf32; k16 chunks double-buffered from pre-permuted g_wp.
// Epilogue fully register-local.
// ---------------------------------------------------------------------------

#define XS_STRIDE 132   // fp32 X (epilogue)
#define XT_STRIDE 136   // tf32 X, k-pair interleaved (mma a-frags)
#define XS_OFF 0
#define XT_OFF (64 * XS_STRIDE)                 // 8448
#define WB_OFF (XT_OFF + 64 * XT_STRIDE)        // 17152
#define WCHUNK 6144
#define BS_OFF (WB_OFF + 2 * WCHUNK)            // 29440
#define SMEM_FLOATS (BS_OFF + 384)              // 29824
#define SMEM_BYTES (SMEM_FLOATS * 4)            // 119296

__device__ __forceinline__ void mma_tf32_k8(float d[4], const unsigned a[4],
                                            unsigned b0, unsigned b1) {
    asm volatile(
        "mma.sync.aligned.m16n8k8.row.col.f32.tf32.tf32.f32 "
        "{%0,%1,%2,%3}, {%4,%5,%6,%7}, {%8,%9}, {%0,%1,%2,%3};"
        : "+f"(d[0]), "+f"(d[1]), "+f"(d[2]), "+f"(d[3])
        : "r"(a[0]), "r"(a[1]), "r"(a[2]), "r"(a[3]), "r"(b0), "r"(b1));
}

__device__ __forceinline__ void cp16(float* dst, const float* src) {
    unsigned s = (unsigned)__cvta_generic_to_shared(dst);
    asm volatile("cp.async.cg.shared.global [%0], [%1], 16;" :: "r"(s), "l"(src));
}

__global__ void __launch_bounds__(512, 1)
fused_main_kernel(const float* __restrict__ x,
                  const float* __restrict__ bf,
                  const float* __restrict__ bi_,
                  const float* __restrict__ bd,
                  float* __restrict__ out) {
    extern __shared__ float sm[];
    float* Xs  = sm + XS_OFF;
    float* XsT = sm + XT_OFF;
    float* Wb  = sm + WB_OFF;
    float* Bs  = sm + BS_OFF;

    int tid = threadIdx.x;
    int bid = blockIdx.x;
    int h  = bid >> 5;
    int w0 = (bid & 31) * 4;

    // ---- load X tile (fp32 copy + tf32 interleaved copy) ----
    for (int i = tid; i < 64 * 32; i += 512) {
        int p = i >> 5, c4 = i & 31;
        int b = p & 15, dw = p >> 4;
        const float4* src =
            (const float4*)(x + (size_t)((b * HH + h) * WW + w0 + dw) * CH2);
        float4 v = src[c4];
        *(float4*)&Xs[p * XS_STRIDE + c4 * 4] = v;
        // k = c4*4 + i ; kg = k/8 = c4>>1 ; e = (k%8)/4 = c4&1 ; p_in = k%4 = i
        int tb = p * XT_STRIDE + (c4 >> 1) * 8 + (c4 & 1);
        XsT[tb + 0] = __uint_as_float(f2tf32(v.x));
        XsT[tb + 2] = __uint_as_float(f2tf32(v.y));
        XsT[tb + 4] = __uint_as_float(f2tf32(v.z));
        XsT[tb + 6] = __uint_as_float(f2tf32(v.w));
    }
    if (tid < 384) {
        int g = tid >> 7, cc = tid & 127;
        Bs[tid] = (g == 0) ? bf[cc] : ((g == 1) ? bi_[cc] : bd[cc]);
    }

    // ---- prologue: stage W chunks 0, 1 ----
    {
        const float4* s0 = (const float4*)(g_wp);
        const float4* s1 = (const float4*)(g_wp + WCHUNK);
        float4* d0 = (float4*)(Wb);
        float4* d1 = (float4*)(Wb + WCHUNK);
#pragma unroll
        for (int j = 0; j < 3; j++) cp16((float*)&d0[tid + j * 512], (const float*)&s0[tid + j * 512]);
        asm volatile("cp.async.commit_group;");
#pragma unroll
        for (int j = 0; j < 3; j++) cp16((float*)&d1[tid + j * 512], (const float*)&s1[tid + j * 512]);
        asm volatile("cp.async.commit_group;");
    }

    int wid = tid >> 5, lane = tid & 31;
    int wm = wid & 1, wn = wid >> 1;          // wm 0..1, wn 0..7
    int gid = lane >> 2, tig = lane & 3;
    int row0 = wm * 32 + gid;

    float acc[12][4];
#pragma unroll
    for (int t = 0; t < 12; t++) {
        acc[t][0] = 0.f; acc[t][1] = 0.f; acc[t][2] = 0.f; acc[t][3] = 0.f;
    }

    // ---- K loop: 8 chunks of k16 ----
    for (int kc = 0; kc < 8; kc++) {
        if (kc < 7) { asm volatile("cp.async.wait_group 1;"); }
        else        { asm volatile("cp.async.wait_group 0;"); }
        __syncthreads();
        const float* Wc = Wb + (kc & 1) * WCHUNK;

#pragma unroll
        for (int g2 = 0; g2 < 2; g2++) {
            int kg = kc * 2 + g2;
            unsigned a[2][4];
#pragma unroll
            for (int mt = 0; mt < 2; mt++) {
                float2 lo = *(const float2*)&XsT[(row0 + mt * 16) * XT_STRIDE + kg * 8 + tig * 2];
                float2 hi = *(const float2*)&XsT[(row0 + mt * 16 + 8) * XT_STRIDE + kg * 8 + tig * 2];
                a[mt][0] = __float_as_uint(lo.x);
                a[mt][1] = __float_as_uint(hi.x);
                a[mt][2] = __float_as_uint(lo.y);
                a[mt][3] = __float_as_uint(hi.y);
            }
#pragma unroll
            for (int b = 0; b < 6; b++) {
                float2 bv = *(const float2*)&Wc[g2 * 3072 + (wn * 48 + b * 8 + gid) * 8 + tig * 2];
                unsigned b0 = __float_as_uint(bv.x);
                unsigned b1 = __float_as_uint(bv.y);
                mma_tf32_k8(acc[b],     a[0], b0, b1);
                mma_tf32_k8(acc[6 + b], a[1], b0, b1);
            }
        }

        if (kc < 6) {
            __syncthreads();   // everyone done reading buffer kc&1
            const float4* s = (const float4*)(g_wp + (kc + 2) * WCHUNK);
            float4* d = (float4*)(Wb + (kc & 1) * WCHUNK);
#pragma unroll
            for (int j = 0; j < 3; j++) cp16((float*)&d[tid + j * 512], (const float*)&s[tid + j * 512]);
            asm volatile("cp.async.commit_group;");
        }
    }

    // ---- epilogue: fully register-local gates -> recurrence -> store ----
    int cbase = wn * 8 + 2 * tig;
#pragma unroll
    for (int mt = 0; mt < 2; mt++) {
#pragma unroll
        for (int r = 0; r < 2; r++) {
            int p = wm * 32 + mt * 16 + gid + r * 8;
            int b_ = p & 15, dw = p >> 4;
            float hro[2], hio[2];
#pragma unroll
            for (int cc = 0; cc < 2; cc++) {
                int c = cbase + cc;
                int ai = r * 2 + cc;
                float zfr = acc[mt * 6 + 0][ai] + Bs[c]       + 2.0f;
                float zfi = acc[mt * 6 + 1][ai] + Bs[64 + c]  + 2.0f;
                float zir = acc[mt * 6 + 2][ai] + Bs[128 + c];
                float zii = acc[mt * 6 + 3][ai] + Bs[192 + c];
                float zdr = acc[mt * 6 + 4][ai] + Bs[256 + c];
                float zdi = acc[mt * 6 + 5][ai] + Bs[320 + c];

                float fgr = 1.0f / (1.0f + __expf(-zfr));
                float fgi = 1.0f / (1.0f + __expf(-zfi));
                float igr = 1.0f / (1.0f + __expf(-zir));
                float igi = 1.0f / (1.0f + __expf(-zii));
                float dr  = 0.1f * (fmaxf(zdr, 0.f) + log1pf(__expf(-fabsf(zdr))));
                float di  = 0.1f * (fmaxf(zdi, 0.f) + log1pf(__expf(-fabsf(zdi))));

                float xr = Xs[p * XS_STRIDE + c];
                float xi = Xs[p * XS_STRIDE + 64 + c];
                float4 f = g_fields[(h * WW + w0 + dw) * CC + c];

                float Bxr = f.z * xr - f.w * xi;
                float Bxi = f.z * xi + f.w * xr;
                float inr = dr * igr * Bxr;
                float ini = di * igi * Bxi;

                float hr = 0.f, hi = 0.f;
#pragma unroll
                for (int t = 0; t < TSTEPS; t++) {
                    float Ahr = f.x * hr - f.y * hi;
                    float Ahi = f.x * hi + f.y * hr;
                    hr = fgr * Ahr + inr;
                    hi = fgi * Ahi + ini;
                }
                hro[cc] = hr; hio[cc] = hi;
            }
            size_t ob = (size_t)((b_ * HH + h) * WW + w0 + dw) * CH2;
            *(float2*)&out[ob + cbase]      = make_float2(hro[0], hro[1]);
            *(float2*)&out[ob + 64 + cbase] = make_float2(hio[0], hio[1]);
        }
    }
}

extern "C" void kernel_launch(void* const* d_in, const int* in_sizes, int n_in,
                              void* d_out, int out_size) {
    const float* x  = (const float*)d_in[0];
    const float* Wf = (const float*)d_in[1];
    const float* bf = (const float*)d_in[2];
    const float* Wi = (const float*)d_in[3];
    const float* bi = (const float*)d_in[4];
    const float* Wd = (const float*)d_in[5];
    const float* bd = (const float*)d_in[6];
    const float* Ar = (const float*)d_in[7];
    const float* Ai = (const float*)d_in[8];
    const float* Br = (const float*)d_in[9];
    const float* Bi = (const float*)d_in[10];
    float* out = (float*)d_out;

    wprep_kernel<<<96, 512>>>(Wf, Wi, Wd);

    static bool attr_set = false;
    if (!attr_set) {
        cudaFuncSetAttribute(fields_kernel,
                             cudaFuncAttributeMaxDynamicSharedMemorySize, 12800 * 4);
        cudaFuncSetAttribute(fused_main_kernel,
                             cudaFuncAttributeMaxDynamicSharedMemorySize, SMEM_BYTES);
        attr_set = true;
    }

    fields_kernel<<<HH * WW / 4, 256, 12800 * 4>>>(Ar, Ai, Br, Bi);
    fused_main_kernel<<<HH * (WW / 4), 512, SMEM_BYTES>>>(x, bf, bi, bd, out);
}

// round 4
// speedup vs baseline: 1.9881x; 1.1350x over previous
#include <cuda_runtime.h>
#include <cstdint>
#include <cstddef>

#define HH 128
#define WW 128
#define CC 64
#define CH2 128
#define TSTEPS 16

// Precomputed frequency-domain fields: {Ar*scale, Ai*scale, Br, Bi} per (h,w,c)
__device__ float4 g_fields[HH * WW * CC];
// Pre-permuted tf32 Wcat, quad layout for LDS.128 b-frags:
// [kc(8)][col'(384)][tig(4)][q(4)] ; k = kc*16 + (q>>1)*8 + tig + (q&1)*4
// col' = wn*48 + bb*8 + r ; gate g=bb/2, ri=bb%2, c = wn*8+r ; src = W_g[k][ri*64+c]
__device__ float g_wp[8 * 6144];

__device__ __forceinline__ unsigned f2tf32(float x) {
    unsigned r;
    asm("cvt.rna.tf32.f32 %0, %1;" : "=r"(r) : "f"(x));
    return r;
}

// ---------------------------------------------------------------------------
// Prep kernel: build g_wp (one-time, 49152 elements)
// ---------------------------------------------------------------------------
__global__ void wprep_kernel(const float* __restrict__ Wf,
                             const float* __restrict__ Wi,
                             const float* __restrict__ Wd) {
    int idx = blockIdx.x * 512 + threadIdx.x;   // 0 .. 49151
    int kc = idx / 6144, r1 = idx % 6144;
    int col = r1 >> 4;
    int tig = (r1 >> 2) & 3;
    int q = r1 & 3;
    int k = kc * 16 + ((q >> 1) << 3) + tig + ((q & 1) << 2);
    int wn = col / 48, bb = (col % 48) >> 3, r = col & 7;
    int g = bb >> 1, ri = bb & 1;
    int c = wn * 8 + r;
    const float* W = (g == 0) ? Wf : ((g == 1) ? Wi : Wd);
    g_wp[idx] = __uint_as_float(f2tf32(W[k * CH2 + ri * 64 + c]));
}

// ---------------------------------------------------------------------------
// Fields kernel: direct DFT of zero-padded 7x7 complex kernels + A stabilization.
// ---------------------------------------------------------------------------
__global__ void fields_kernel(const float* __restrict__ A_real,
                              const float* __restrict__ A_imag,
                              const float* __restrict__ B_real,
                              const float* __restrict__ B_imag) {
    extern __shared__ float fs[];
    float* sAr = fs;                 // 3136
    float* sAi = fs + 3136;
    float* sBr = fs + 6272;
    float* sBi = fs + 9408;
    float* ct  = fs + 12544;         // 128
    float* st  = fs + 12672;         // 128

    int tid = threadIdx.x;
    for (int i = tid; i < 3136; i += 256) {
        sAr[i] = A_real[i]; sAi[i] = A_imag[i];
        sBr[i] = B_real[i]; sBi[i] = B_imag[i];
    }
    if (tid < 128) {
        float s, co;
        sincospif((float)tid * (1.0f / 64.0f), &s, &co);
        ct[tid] = co; st[tid] = s;
    }
    __syncthreads();

    int c = tid & 63, lc = tid >> 6;
    int uv = blockIdx.x * 4 + lc;
    int u = uv >> 7, v = uv & 127;

    float ar = 0.f, ai = 0.f, br = 0.f, bi = 0.f;
    int base = c * 49;
#pragma unroll
    for (int p = 0; p < 7; p++) {
#pragma unroll
        for (int q = 0; q < 7; q++) {
            int m = (u * (p + 60) + v * (q + 60)) & 127;
            float co = ct[m], si = st[m];
            float kr = sAr[base + p * 7 + q];
            float ki = sAi[base + p * 7 + q];
            ar += kr * co + ki * si;
            ai += ki * co - kr * si;
            kr = sBr[base + p * 7 + q];
            ki = sBi[base + p * 7 + q];
            br += kr * co + ki * si;
            bi += ki * co - kr * si;
        }
    }
    float mag = sqrtf(ar * ar + ai * ai + 1e-8f);
    float scale = 0.95f * (1.0f / (1.0f + __expf(-mag))) / (mag + 1e-8f);
    g_fields[uv * CC + c] = make_float4(ar * scale, ai * scale, br, bi);
}

// ---------------------------------------------------------------------------
// Fused main kernel.
// CTA: 512 threads, 64 positions (16 b x 4 w at fixed h).
// 16 warps = wm(2) x wn(8); warp tile m32 x n48 (permuted cols, 6 gate blocks).
// mma m16n8k8 tf32; k16 chunks, 3-buffer cp.async ring, LDS.128 fragments.
// Epilogue: register-local gates + log-depth (doubling) recurrence.
// ---------------------------------------------------------------------------

#define XS_STRIDE 132   // fp32 X (epilogue)
#define XT2_STRIDE 144  // tf32 X quad layout (stride % 32 == 16 -> conflict-free LDS.128)
#define XS_OFF 0
#define XT_OFF (64 * XS_STRIDE)                 // 8448
#define WB_OFF (XT_OFF + 64 * XT2_STRIDE)       // 17664
#define WCHUNK 6144
#define BS_OFF (WB_OFF + 3 * WCHUNK)            // 36096
#define SMEM_FLOATS (BS_OFF + 384)              // 36480
#define SMEM_BYTES (SMEM_FLOATS * 4)            // 145920

__device__ __forceinline__ void mma_tf32_k8(float d[4], const unsigned a[4],
                                            unsigned b0, unsigned b1) {
    asm volatile(
        "mma.sync.aligned.m16n8k8.row.col.f32.tf32.tf32.f32 "
        "{%0,%1,%2,%3}, {%4,%5,%6,%7}, {%8,%9}, {%0,%1,%2,%3};"
        : "+f"(d[0]), "+f"(d[1]), "+f"(d[2]), "+f"(d[3])
        : "r"(a[0]), "r"(a[1]), "r"(a[2]), "r"(a[3]), "r"(b0), "r"(b1));
}

__device__ __forceinline__ void cp16(float* dst, const float* src) {
    unsigned s = (unsigned)__cvta_generic_to_shared(dst);
    asm volatile("cp.async.cg.shared.global [%0], [%1], 16;" :: "r"(s), "l"(src));
}

__device__ __forceinline__ void stage_chunk(float* dst, const float* src, int tid) {
#pragma unroll
    for (int j = 0; j < 3; j++) {
        int i = (tid + j * 512) * 4;
        cp16(dst + i, src + i);
    }
}

__global__ void __launch_bounds__(512, 1)
fused_main_kernel(const float* __restrict__ x,
                  const float* __restrict__ bf,
                  const float* __restrict__ bi_,
                  const float* __restrict__ bd,
                  float* __restrict__ out) {
    extern __shared__ float sm[];
    float* Xs  = sm + XS_OFF;
    float* XsT = sm + XT_OFF;
    float* Wb  = sm + WB_OFF;
    float* Bs  = sm + BS_OFF;

    int tid = threadIdx.x;
    int bid = blockIdx.x;
    int h  = bid >> 5;
    int w0 = (bid & 31) * 4;

    // ---- load X tile (fp32 copy + tf32 quad-layout copy) ----
    for (int i = tid; i < 64 * 32; i += 512) {
        int p = i >> 5, c4 = i & 31;
        int b = p & 15, dw = p >> 4;
        const float4* src =
            (const float4*)(x + (size_t)((b * HH + h) * WW + w0 + dw) * CH2);
        float4 v = src[c4];
        *(float4*)&Xs[p * XS_STRIDE + c4 * 4] = v;
        // k = c4*4 + j  ->  idx_in_row = (c4>>2)*16 + j*4 + (c4&3)
        int tb = p * XT2_STRIDE + (c4 >> 2) * 16 + (c4 & 3);
        XsT[tb + 0]  = __uint_as_float(f2tf32(v.x));
        XsT[tb + 4]  = __uint_as_float(f2tf32(v.y));
        XsT[tb + 8]  = __uint_as_float(f2tf32(v.z));
        XsT[tb + 12] = __uint_as_float(f2tf32(v.w));
    }
    if (tid < 384) {
        int g = tid >> 7, cc = tid & 127;
        Bs[tid] = (g == 0) ? bf[cc] : ((g == 1) ? bi_[cc] : bd[cc]);
    }

    // ---- prologue: stage W chunks 0, 1 into ring buffers 0, 1 ----
    stage_chunk(Wb, g_wp, tid);
    asm volatile("cp.async.commit_group;");
    stage_chunk(Wb + WCHUNK, g_wp + WCHUNK, tid);
    asm volatile("cp.async.commit_group;");

    int wid = tid >> 5, lane = tid & 31;
    int wm = wid & 1, wn = wid >> 1;          // wm 0..1, wn 0..7
    int gid = lane >> 2, tig = lane & 3;
    int row0 = wm * 32 + gid;

    float acc[12][4];
#pragma unroll
    for (int t = 0; t < 12; t++) {
        acc[t][0] = 0.f; acc[t][1] = 0.f; acc[t][2] = 0.f; acc[t][3] = 0.f;
    }

    // ---- K loop: 8 chunks of k16, 3-buffer ring, 1 barrier per chunk ----
    for (int kc = 0; kc < 8; kc++) {
        if (kc < 7) { asm volatile("cp.async.wait_group 1;"); }
        else        { asm volatile("cp.async.wait_group 0;"); }
        __syncthreads();   // chunk kc visible everywhere; buffer (kc+2)%3 free
        if (kc < 6) {
            stage_chunk(Wb + ((kc + 2) % 3) * WCHUNK, g_wp + (kc + 2) * WCHUNK, tid);
            asm volatile("cp.async.commit_group;");
        }
        const float* Wc = Wb + (kc % 3) * WCHUNK;

        // a-frags: 4 x LDS.128 covering full k16
        float4 xa0 = *(const float4*)&XsT[(row0     ) * XT2_STRIDE + kc * 16 + tig * 4];
        float4 xa1 = *(const float4*)&XsT[(row0 +  8) * XT2_STRIDE + kc * 16 + tig * 4];
        float4 xa2 = *(const float4*)&XsT[(row0 + 16) * XT2_STRIDE + kc * 16 + tig * 4];
        float4 xa3 = *(const float4*)&XsT[(row0 + 24) * XT2_STRIDE + kc * 16 + tig * 4];
        unsigned aE0[4] = {__float_as_uint(xa0.x), __float_as_uint(xa1.x),
                           __float_as_uint(xa0.y), __float_as_uint(xa1.y)};
        unsigned aO0[4] = {__float_as_uint(xa0.z), __float_as_uint(xa1.z),
                           __float_as_uint(xa0.w), __float_as_uint(xa1.w)};
        unsigned aE1[4] = {__float_as_uint(xa2.x), __float_as_uint(xa3.x),
                           __float_as_uint(xa2.y), __float_as_uint(xa3.y)};
        unsigned aO1[4] = {__float_as_uint(xa2.z), __float_as_uint(xa3.z),
                           __float_as_uint(xa2.w), __float_as_uint(xa3.w)};

#pragma unroll
        for (int b = 0; b < 6; b++) {
            float4 bv = *(const float4*)&Wc[(wn * 48 + b * 8 + gid) * 16 + tig * 4];
            unsigned b0 = __float_as_uint(bv.x), b1 = __float_as_uint(bv.y);
            unsigned b2 = __float_as_uint(bv.z), b3 = __float_as_uint(bv.w);
            mma_tf32_k8(acc[b],     aE0, b0, b1);
            mma_tf32_k8(acc[b],     aO0, b2, b3);
            mma_tf32_k8(acc[6 + b], aE1, b0, b1);
            mma_tf32_k8(acc[6 + b], aO1, b2, b3);
        }
    }

    // ---- epilogue: register-local gates -> log-depth recurrence -> store ----
    int cbase = wn * 8 + 2 * tig;
#pragma unroll
    for (int mt = 0; mt < 2; mt++) {
#pragma unroll
        for (int r = 0; r < 2; r++) {
            int p = wm * 32 + mt * 16 + gid + r * 8;
            int b_ = p & 15, dw = p >> 4;
            float hro[2], hio[2];
#pragma unroll
            for (int cc = 0; cc < 2; cc++) {
                int c = cbase + cc;
                int ai = r * 2 + cc;
                float zfr = acc[mt * 6 + 0][ai] + Bs[c]       + 2.0f;
                float zfi = acc[mt * 6 + 1][ai] + Bs[64 + c]  + 2.0f;
                float zir = acc[mt * 6 + 2][ai] + Bs[128 + c];
                float zii = acc[mt * 6 + 3][ai] + Bs[192 + c];
                float zdr = acc[mt * 6 + 4][ai] + Bs[256 + c];
                float zdi = acc[mt * 6 + 5][ai] + Bs[320 + c];

                float fgr = 1.0f / (1.0f + __expf(-zfr));
                float fgi = 1.0f / (1.0f + __expf(-zfi));
                float igr = 1.0f / (1.0f + __expf(-zir));
                float igi = 1.0f / (1.0f + __expf(-zii));
                float dr  = 0.1f * (fmaxf(zdr, 0.f) + log1pf(__expf(-fabsf(zdr))));
                float di  = 0.1f * (fmaxf(zdi, 0.f) + log1pf(__expf(-fabsf(zdi))));

                float xr = Xs[p * XS_STRIDE + c];
                float xi = Xs[p * XS_STRIDE + 64 + c];
                float4 f = g_fields[(h * WW + w0 + dw) * CC + c];

                float Bxr = f.z * xr - f.w * xi;
                float Bxi = f.z * xi + f.w * xr;
                float vr = dr * igr * Bxr;    // inp_r
                float vi = di * igi * Bxi;    // inp_i

                // M = [[fgr*Ar, -fgr*Ai],[fgi*Ai, fgi*Ar]]
                float m00 = fgr * f.x, m01 = -(fgr * f.y);
                float m10 = fgi * f.y, m11 = fgi * f.x;

                // powers M^2, M^4, M^8 via squaring
                float p00 = m00, p01 = m01, p10 = m10, p11 = m11;
                float q00[3], q01[3], q10[3], q11[3];
#pragma unroll
                for (int j = 0; j < 3; j++) {
                    float s = p00 + p11;
                    float t = p01 * p10;
                    q00[j] = fmaf(p00, p00, t);
                    q01[j] = p01 * s;
                    q10[j] = p10 * s;
                    q11[j] = fmaf(p11, p11, t);
                    p00 = q00[j]; p01 = q01[j]; p10 = q10[j]; p11 = q11[j];
                }
                // h = (I+M)(I+M^2)(I+M^4)(I+M^8) * inp  (right-to-left)
                float nvr, nvi;
                nvr = fmaf(q01[2], vi, fmaf(q00[2], vr, vr));
                nvi = fmaf(q11[2], vi, fmaf(q10[2], vr, vi));
                vr = nvr; vi = nvi;
                nvr = fmaf(q01[1], vi, fmaf(q00[1], vr, vr));
                nvi = fmaf(q11[1], vi, fmaf(q10[1], vr, vi));
                vr = nvr; vi = nvi;
                nvr = fmaf(q01[0], vi, fmaf(q00[0], vr, vr));
                nvi = fmaf(q11[0], vi, fmaf(q10[0], vr, vi));
                vr = nvr; vi = nvi;
                nvr = fmaf(m01, vi, fmaf(m00, vr, vr));
                nvi = fmaf(m11, vi, fmaf(m10, vr, vi));

                hro[cc] = nvr; hio[cc] = nvi;
            }
            size_t ob = (size_t)((b_ * HH + h) * WW + w0 + dw) * CH2;
            *(float2*)&out[ob + cbase]      = make_float2(hro[0], hro[1]);
            *(float2*)&out[ob + 64 + cbase] = make_float2(hio[0], hio[1]);
        }
    }
}

extern "C" void kernel_launch(void* const* d_in, const int* in_sizes, int n_in,
                              void* d_out, int out_size) {
    const float* x  = (const float*)d_in[0];
    const float* Wf = (const float*)d_in[1];
    const float* bf = (const float*)d_in[2];
    const float* Wi = (const float*)d_in[3];
    const float* bi = (const float*)d_in[4];
    const float* Wd = (const float*)d_in[5];
    const float* bd = (const float*)d_in[6];
    const float* Ar = (const float*)d_in[7];
    const float* Ai = (const float*)d_in[8];
    const float* Br = (const float*)d_in[9];
    const float* Bi = (const float*)d_in[10];
    float* out = (float*)d_out;

    wprep_kernel<<<96, 512>>>(Wf, Wi, Wd);

    static bool attr_set = false;
    if (!attr_set) {
        cudaFuncSetAttribute(fields_kernel,
                             cudaFuncAttributeMaxDynamicSharedMemorySize, 12800 * 4);
        cudaFuncSetAttribute(fused_main_kernel,
                             cudaFuncAttributeMaxDynamicSharedMemorySize, SMEM_BYTES);
        attr_set = true;
    }

    fields_kernel<<<HH * WW / 4, 256, 12800 * 4>>>(Ar, Ai, Br, Bi);
    fused_main_kernel<<<HH * (WW / 4), 512, SMEM_BYTES>>>(x, bf, bi, bd, out);
}